// round 15
// baseline (speedup 1.0000x reference)
#include <cuda_runtime.h>
#include <cuda_fp16.h>
#include <math.h>
#include <stdint.h>
#include <string.h>

#define BQ      4
#define LSEQ    2048
#define DMODEL  512
#define NHEAD   8
#define HDIM    64
#define FFND    2048
#define BL      (BQ * LSEQ)
#define QKV3    (3 * DMODEL)
#define SCHUNK  512

// Scratch (static device globals)
__device__ __half g_qkvh [BL * QKV3];
__device__ __half g_attnh[BL * DMODEL];
__device__ __half g_ffnh [BL * FFND];
__device__ __half g_xh   [BL * DMODEL];
__device__ __half g_x1h  [BL * DMODEL];
__device__ float  g_x1   [BL * DMODEL];
__device__ float  g_pre  [BL * DMODEL];
__device__ __half g_qkvwT[QKV3 * DMODEL];
__device__ __half g_outwT[DMODEL * DMODEL];
__device__ __half g_ffn1T[FFND * DMODEL];
__device__ __half g_ffn2T[DMODEL * FFND];

// ---------------------------------------------------------------------------
__device__ __forceinline__ uint32_t h2u(__half2 h) {
    uint32_t u; memcpy(&u, &h, 4); return u;
}
__device__ __forceinline__ void mma_f16(float* d, const uint32_t* a, const uint32_t* b) {
    asm volatile(
        "mma.sync.aligned.m16n8k16.row.col.f32.f16.f16.f32 "
        "{%0,%1,%2,%3}, {%4,%5,%6,%7}, {%8,%9}, {%0,%1,%2,%3};"
        : "+f"(d[0]), "+f"(d[1]), "+f"(d[2]), "+f"(d[3])
        : "r"(a[0]), "r"(a[1]), "r"(a[2]), "r"(a[3]), "r"(b[0]), "r"(b[1]));
}
__device__ __forceinline__ uint32_t smaddr(const void* p) {
    uint32_t a;
    asm("{.reg .u64 t; cvta.to.shared.u64 t, %1; cvt.u32.u64 %0, t;}" : "=r"(a) : "l"(p));
    return a;
}
#define CP16(dst, src) asm volatile("cp.async.cg.shared.global [%0], [%1], 16;" :: "r"(dst), "l"(src))
#define CPCOMMIT()     asm volatile("cp.async.commit_group;")
#define CPWAIT(n)      asm volatile("cp.async.wait_group %0;" :: "n"(n))
#define LDSM_X4(r0,r1,r2,r3,a) \
    asm volatile("ldmatrix.sync.aligned.m8n8.x4.shared.b16 {%0,%1,%2,%3}, [%4];" \
        : "=r"(r0), "=r"(r1), "=r"(r2), "=r"(r3) : "r"(a))
#define LDSM_X4T(r0,r1,r2,r3,a) \
    asm volatile("ldmatrix.sync.aligned.m8n8.x4.trans.shared.b16 {%0,%1,%2,%3}, [%4];" \
        : "=r"(r0), "=r"(r1), "=r"(r2), "=r"(r3) : "r"(a))

// ---------------------------------------------------------------------------
// FP16 tensor GEMM: 128x128 block, 4 warps (2x2), warp tile 64x64,
// BK=64 (halves per-iter barrier cost vs BK=32), 3-stage cp.async,
// 128 thr, 2 CTAs/SM. LDA_=72 halves (144B rows, LDSM conflict-free).
// ---------------------------------------------------------------------------
#define LDA_ 72
#define A_STAGE (128 * LDA_ * 2)       // 18432 B per stage per operand
#define NSTAGE  3
#define GSMEM   (2 * NSTAGE * A_STAGE) // 110592

template<int GELU, int HASRES, int OUTH>
__global__ __launch_bounds__(128, 2) void hgemm_kernel(
    const __half* __restrict__ A, const __half* __restrict__ BT,
    const float* __restrict__ bias, const float* __restrict__ res,
    __half* __restrict__ Ch, float* __restrict__ Cf, int M, int N, int K)
{
    extern __shared__ __half smem_dyn[];

    const int tid   = threadIdx.x;
    const int lane  = tid & 31, wid = tid >> 5;
    const int grp   = lane >> 2, qd = lane & 3;
    const int g     = lane >> 3, l7 = lane & 7;
    const int mBase = blockIdx.y * 128;
    const int nBase = blockIdx.x * 128;
    const int mWarp = (wid & 1) * 64;
    const int nWarp = (wid >> 1) * 64;

    const uint32_t aBase = smaddr(smem_dyn);
    const uint32_t bBase = aBase + NSTAGE * A_STAGE;

    // staging: 8 chunks per operand per thread; c = tid + i*128,
    // row = c>>3 (0..127), seg = (c&7)*8 halves (BK=64 -> 8 segs/row)
    const __half* Ap[8]; const __half* Bp[8];
    uint32_t sAo[8], sBo[8];
#pragma unroll
    for (int i = 0; i < 8; i++) {
        const int c = tid + i * 128;
        const int r = c >> 3, s = (c & 7) * 8;
        Ap[i]  = A  + (size_t)(mBase + r) * K + s;
        Bp[i]  = BT + (size_t)(nBase + r) * K + s;
        sAo[i] = aBase + (r * LDA_ + s) * 2;
        sBo[i] = bBase + (r * LDA_ + s) * 2;
    }

    const int rowA = mWarp + (g & 1) * 8 + l7;
    const int kA   = (g >> 1) * 8;
    const int rowB = nWarp + (g >> 1) * 8 + l7;
    const int kB   = (g & 1) * 8;

    float acc[4][8][4];
#pragma unroll
    for (int mt = 0; mt < 4; mt++)
#pragma unroll
        for (int nt = 0; nt < 8; nt++)
#pragma unroll
            for (int f = 0; f < 4; f++) acc[mt][nt][f] = 0.f;

    const int niter = K >> 6;

#pragma unroll
    for (int s = 0; s < NSTAGE - 1; s++) {
        if (s < niter) {
            const int k0 = s << 6;
            const uint32_t o = s * A_STAGE;
#pragma unroll
            for (int i = 0; i < 8; i++) {
                CP16(sAo[i] + o, Ap[i] + k0);
                CP16(sBo[i] + o, Bp[i] + k0);
            }
        }
        CPCOMMIT();
    }

    int slot = 0;
    for (int it = 0; it < niter; it++) {
        CPWAIT(NSTAGE - 2);
        __syncthreads();

        if (it + NSTAGE - 1 < niter) {
            const int k0 = (it + NSTAGE - 1) << 6;
            int islot = slot + NSTAGE - 1; if (islot >= NSTAGE) islot -= NSTAGE;
            const uint32_t o = islot * A_STAGE;
#pragma unroll
            for (int i = 0; i < 8; i++) {
                CP16(sAo[i] + o, Ap[i] + k0);
                CP16(sBo[i] + o, Bp[i] + k0);
            }
        }
        CPCOMMIT();

        const uint32_t aS = aBase + slot * A_STAGE;
        const uint32_t bS = bBase + slot * A_STAGE;
#pragma unroll
        for (int ks = 0; ks < 64; ks += 16) {
            uint32_t af[4][4], bf[8][2];
#pragma unroll
            for (int mt = 0; mt < 4; mt++)
                LDSM_X4(af[mt][0], af[mt][1], af[mt][2], af[mt][3],
                        aS + (((rowA + mt * 16) * LDA_) + ks + kA) * 2);
#pragma unroll
            for (int j = 0; j < 4; j++)
                LDSM_X4(bf[2 * j][0], bf[2 * j][1], bf[2 * j + 1][0], bf[2 * j + 1][1],
                        bS + (((rowB + j * 16) * LDA_) + ks + kB) * 2);
#pragma unroll
            for (int mt = 0; mt < 4; mt++)
#pragma unroll
                for (int nt = 0; nt < 8; nt++)
                    mma_f16(acc[mt][nt], af[mt], bf[nt]);
        }
        slot++; if (slot >= NSTAGE) slot = 0;
    }

#pragma unroll
    for (int mt = 0; mt < 4; mt++) {
#pragma unroll
        for (int nt = 0; nt < 8; nt++) {
            const int row = mBase + mWarp + mt * 16 + grp;
            const int col = nBase + nWarp + nt * 8 + qd * 2;
            const float b0 = bias[col], b1 = bias[col + 1];
#pragma unroll
            for (int rr = 0; rr < 2; rr++) {
                const int r = row + rr * 8;
                const size_t base = (size_t)r * N + col;
                float v0 = acc[mt][nt][rr * 2 + 0] + b0;
                float v1 = acc[mt][nt][rr * 2 + 1] + b1;
                if (GELU) {
                    v0 = 0.5f * v0 * (1.0f + erff(v0 * 0.70710678118654752f));
                    v1 = 0.5f * v1 * (1.0f + erff(v1 * 0.70710678118654752f));
                }
                if (HASRES) {
                    float2 rv = *(const float2*)(res + base);
                    v0 += rv.x; v1 += rv.y;
                }
                if (OUTH) {
                    *(__half2*)(Ch + base) = __floats2half2_rn(v0, v1);
                } else {
                    float2 o; o.x = v0; o.y = v1;
                    *(float2*)(Cf + base) = o;
                }
            }
        }
    }
}

// ---------------------------------------------------------------------------
// Merged prep: f2h of x + 4 weight transposes in one launch.
// ---------------------------------------------------------------------------
__global__ __launch_bounds__(256) void prep_kernel(
    const float* __restrict__ x,
    const float* __restrict__ qkv_w, const float* __restrict__ out_w,
    const float* __restrict__ ffn_w1, const float* __restrict__ ffn_w2,
    __half* __restrict__ xh, __half* __restrict__ qkvwT, __half* __restrict__ outwT,
    __half* __restrict__ ffn1T, __half* __restrict__ ffn2T)
{
    int bid = blockIdx.x;
    if (bid < 4096) {
        const int i = bid * 1024 + threadIdx.x * 4;
        float4 v = *(const float4*)(x + i);
        *(__half2*)(xh + i)     = __floats2half2_rn(v.x, v.y);
        *(__half2*)(xh + i + 2) = __floats2half2_rn(v.z, v.w);
        return;
    }
    bid -= 4096;
    const float* in; __half* outp; int C, t, R;
    if (bid < 768)       { in = qkv_w;  outp = qkvwT; R = DMODEL; C = QKV3;   t = bid; }
    else if (bid < 1024) { in = out_w;  outp = outwT; R = DMODEL; C = DMODEL; t = bid - 768; }
    else if (bid < 2048) { in = ffn_w1; outp = ffn1T; R = DMODEL; C = FFND;   t = bid - 1024; }
    else                 { in = ffn_w2; outp = ffn2T; R = FFND;   C = DMODEL; t = bid - 2048; }
    const int tilesC = C >> 5;
    const int cb = (t % tilesC) * 32, rb = (t / tilesC) * 32;

    __shared__ float tt[32][33];
    const int tx = threadIdx.x & 31, ty = threadIdx.x >> 5;
#pragma unroll
    for (int j = 0; j < 4; j++)
        tt[ty + j * 8][tx] = in[(size_t)(rb + ty + j * 8) * C + cb + tx];
    __syncthreads();
#pragma unroll
    for (int j = 0; j < 4; j++)
        outp[(size_t)(cb + ty + j * 8) * R + rb + tx] = __float2half(tt[tx][ty + j * 8]);
}

// ---------------------------------------------------------------------------
// FP16 flash attention: register P, ldmatrix frags, 3-stage cp.async KV
// pipeline, single barrier per tile, wave-balance remap, base-2 softmax
// (score scale folds in log2e; exp2f replaces __expf).
// ---------------------------------------------------------------------------
#define LDK_ 72
#define KV_STAGE (32 * LDK_ * 2)
#define ANSTG 3
#define SCALE2 0.18033688011112042f   // 0.125 * log2(e)

__device__ __forceinline__ float qmax4(float v) {
    v = fmaxf(v, __shfl_xor_sync(0xffffffffu, v, 1));
    v = fmaxf(v, __shfl_xor_sync(0xffffffffu, v, 2));
    return v;
}
__device__ __forceinline__ float qsum4(float v) {
    v += __shfl_xor_sync(0xffffffffu, v, 1);
    v += __shfl_xor_sync(0xffffffffu, v, 2);
    return v;
}

__global__ __launch_bounds__(128, 2) void attn_h_kernel(
    const __half* __restrict__ qkv, const int* __restrict__ mask,
    __half* __restrict__ out)
{
    __shared__ __half Ks[ANSTG][32 * LDK_];
    __shared__ __half Vs[ANSTG][32 * LDK_];
    __shared__ float biasS[ANSTG][32];

    // Wave-balance remap: idx<256 -> interior chunks c=1,2; else edges c=0,3.
    int idx = blockIdx.x;
    int c, rest;
    if (idx < 256) { c = 1 + (idx & 1); rest = idx >> 1; }
    else           { idx -= 256; c = 3 * (idx & 1); rest = idx >> 1; }
    const int qt = rest & 3;
    const int bh = rest >> 2;
    const int b  = bh >> 3, h = bh & 7;

    const int tid = threadIdx.x, lane = tid & 31, wid = tid >> 5;
    const int grp = lane >> 2, qd = lane & 3;
    const int g   = lane >> 3, l7 = lane & 7;
    const int lq0 = c * SCHUNK + qt * 128 + wid * 32;

    const uint32_t kBase = smaddr(Ks);
    const uint32_t vBase = smaddr(Vs);

    const int rowK = (g >> 1) * 8 + l7;
    const int kK   = (g & 1) * 8;
    const int rowV = (g & 1) * 8 + l7;
    const int colV = (g >> 1) * 8;

    const int stRow = (tid & 63) >> 1;
    const int stSeg = (tid & 1) * 32;
    const int isV   = tid >> 6;
    const uint32_t stDst = (isV ? vBase : kBase) + (stRow * LDK_ + stSeg) * 2;
    const size_t   stSrcOff = (size_t)DMODEL + (size_t)isV * DMODEL + h * HDIM + stSeg;

    uint32_t qa[2][4][4];
#pragma unroll
    for (int mt = 0; mt < 2; mt++)
#pragma unroll
        for (int ks = 0; ks < 4; ks++) {
            const __half* q0 = qkv + (size_t)(b * LSEQ + lq0 + mt * 16 + grp) * QKV3
                               + h * HDIM + ks * 16 + 2 * qd;
            qa[mt][ks][0] = *(const uint32_t*)(q0);
            qa[mt][ks][1] = *(const uint32_t*)(q0 + (size_t)8 * QKV3);
            qa[mt][ks][2] = *(const uint32_t*)(q0 + 8);
            qa[mt][ks][3] = *(const uint32_t*)(q0 + (size_t)8 * QKV3 + 8);
        }

    float O[2][8][4];
#pragma unroll
    for (int mt = 0; mt < 2; mt++)
#pragma unroll
        for (int nt = 0; nt < 8; nt++)
#pragma unroll
            for (int f = 0; f < 4; f++) O[mt][nt][f] = 0.f;
    float mrow[2][2] = {{-1e30f, -1e30f}, {-1e30f, -1e30f}};
    float lrow[2][2] = {{0.f, 0.f}, {0.f, 0.f}};

    int k0 = (c - 1) * SCHUNK; if (k0 < 0) k0 = 0;
    int k1 = (c + 2) * SCHUNK; if (k1 > LSEQ) k1 = LSEQ;
    const int niter = (k1 - k0) >> 5;

#pragma unroll
    for (int s = 0; s < ANSTG - 1; s++) {
        if (s < niter) {
            const int kt = k0 + s * 32;
            const __half* src = qkv + (size_t)(b * LSEQ + kt + stRow) * QKV3 + stSrcOff;
            const uint32_t d = stDst + s * KV_STAGE;
            CP16(d,      src);
            CP16(d + 16, src + 8);
            CP16(d + 32, src + 16);
            CP16(d + 48, src + 24);
            if (tid < 32) biasS[s][tid] = mask[b * LSEQ + kt + tid] ? -1e30f : 0.f;
        }
        CPCOMMIT();
    }

    int slot = 0;
    for (int it = 0; it < niter; it++) {
        CPWAIT(ANSTG - 2);
        __syncthreads();

        if (it + ANSTG - 1 < niter) {
            const int ktn = k0 + (it + ANSTG - 1) * 32;
            int islot = slot + ANSTG - 1; if (islot >= ANSTG) islot -= ANSTG;
            const __half* src = qkv + (size_t)(b * LSEQ + ktn + stRow) * QKV3 + stSrcOff;
            const uint32_t d = stDst + islot * KV_STAGE;
            CP16(d,      src);
            CP16(d + 16, src + 8);
            CP16(d + 32, src + 16);
            CP16(d + 48, src + 24);
            if (tid < 32) biasS[islot][tid] = mask[b * LSEQ + ktn + tid] ? -1e30f : 0.f;
        }
        CPCOMMIT();

        const uint32_t kS = kBase + slot * KV_STAGE;
        const uint32_t vS = vBase + slot * KV_STAGE;

        float sc[2][4][4];
#pragma unroll
        for (int mt = 0; mt < 2; mt++)
#pragma unroll
            for (int nt = 0; nt < 4; nt++)
#pragma unroll
                for (int f = 0; f < 4; f++) sc[mt][nt][f] = 0.f;
#pragma unroll
        for (int ks = 0; ks < 4; ks++) {
            uint32_t kb[4][2];
            LDSM_X4(kb[0][0], kb[0][1], kb[1][0], kb[1][1],
                    kS + ((rowK * LDK_) + ks * 16 + kK) * 2);
            LDSM_X4(kb[2][0], kb[2][1], kb[3][0], kb[3][1],
                    kS + (((rowK + 16) * LDK_) + ks * 16 + kK) * 2);
#pragma unroll
            for (int mt = 0; mt < 2; mt++)
#pragma unroll
                for (int nt = 0; nt < 4; nt++)
                    mma_f16(sc[mt][nt], qa[mt][ks], kb[nt]);
        }

        // scale into log2 domain + mask
        float bs0[4], bs1[4];
#pragma unroll
        for (int nt = 0; nt < 4; nt++) {
            bs0[nt] = biasS[slot][nt * 8 + 2 * qd];
            bs1[nt] = biasS[slot][nt * 8 + 2 * qd + 1];
        }
#pragma unroll
        for (int mt = 0; mt < 2; mt++)
#pragma unroll
            for (int nt = 0; nt < 4; nt++) {
                sc[mt][nt][0] = sc[mt][nt][0] * SCALE2 + bs0[nt];
                sc[mt][nt][1] = sc[mt][nt][1] * SCALE2 + bs1[nt];
                sc[mt][nt][2] = sc[mt][nt][2] * SCALE2 + bs0[nt];
                sc[mt][nt][3] = sc[mt][nt][3] * SCALE2 + bs1[nt];
            }

        float scl[2][2];
#pragma unroll
        for (int mt = 0; mt < 2; mt++) {
            float nm0 = -1e30f, nm1 = -1e30f;
#pragma unroll
            for (int nt = 0; nt < 4; nt++) {
                nm0 = fmaxf(nm0, fmaxf(sc[mt][nt][0], sc[mt][nt][1]));
                nm1 = fmaxf(nm1, fmaxf(sc[mt][nt][2], sc[mt][nt][3]));
            }
            nm0 = qmax4(nm0); nm1 = qmax4(nm1);
            const float m0 = fmaxf(mrow[mt][0], nm0);
            const float m1 = fmaxf(mrow[mt][1], nm1);
            scl[mt][0] = exp2f(mrow[mt][0] - m0);
            scl[mt][1] = exp2f(mrow[mt][1] - m1);
            lrow[mt][0] *= scl[mt][0];
            lrow[mt][1] *= scl[mt][1];
            mrow[mt][0] = m0; mrow[mt][1] = m1;
        }
#pragma unroll
        for (int mt = 0; mt < 2; mt++)
#pragma unroll
            for (int nt = 0; nt < 8; nt++) {
                O[mt][nt][0] *= scl[mt][0];
                O[mt][nt][1] *= scl[mt][0];
                O[mt][nt][2] *= scl[mt][1];
                O[mt][nt][3] *= scl[mt][1];
            }

        uint32_t pf[2][2][4];
        float rs[2][2] = {{0.f, 0.f}, {0.f, 0.f}};
#pragma unroll
        for (int mt = 0; mt < 2; mt++)
#pragma unroll
            for (int nt = 0; nt < 4; nt++) {
                const float p0 = exp2f(sc[mt][nt][0] - mrow[mt][0]);
                const float p1 = exp2f(sc[mt][nt][1] - mrow[mt][0]);
                const float p2 = exp2f(sc[mt][nt][2] - mrow[mt][1]);
                const float p3 = exp2f(sc[mt][nt][3] - mrow[mt][1]);
                rs[mt][0] += p0 + p1;
                rs[mt][1] += p2 + p3;
                const int ks = nt >> 1, hf = nt & 1;
                pf[mt][ks][hf * 2 + 0] = h2u(__floats2half2_rn(p0, p1));
                pf[mt][ks][hf * 2 + 1] = h2u(__floats2half2_rn(p2, p3));
            }
#pragma unroll
        for (int mt = 0; mt < 2; mt++) {
            lrow[mt][0] += qsum4(rs[mt][0]);
            lrow[mt][1] += qsum4(rs[mt][1]);
        }

#pragma unroll
        for (int ks = 0; ks < 2; ks++) {
            uint32_t vb[8][2];
#pragma unroll
            for (int ntp = 0; ntp < 8; ntp += 2)
                LDSM_X4T(vb[ntp][0], vb[ntp][1], vb[ntp + 1][0], vb[ntp + 1][1],
                         vS + (((ks * 16 + rowV) * LDK_) + ntp * 8 + colV) * 2);
#pragma unroll
            for (int mt = 0; mt < 2; mt++)
#pragma unroll
                for (int nt = 0; nt < 8; nt++)
                    mma_f16(O[mt][nt], pf[mt][ks], vb[nt]);
        }
        slot++; if (slot >= ANSTG) slot = 0;
    }

#pragma unroll
    for (int mt = 0; mt < 2; mt++) {
        const float inv0 = 1.0f / lrow[mt][0];
        const float inv1 = 1.0f / lrow[mt][1];
#pragma unroll
        for (int nt = 0; nt < 8; nt++) {
            const int row = lq0 + mt * 16 + grp;
            const int col = h * HDIM + nt * 8 + 2 * qd;
            *(__half2*)(out + (size_t)(b * LSEQ + row) * DMODEL + col) =
                __floats2half2_rn(O[mt][nt][0] * inv0, O[mt][nt][1] * inv0);
            *(__half2*)(out + (size_t)(b * LSEQ + row + 8) * DMODEL + col) =
                __floats2half2_rn(O[mt][nt][2] * inv1, O[mt][nt][3] * inv1);
        }
    }
}

// ---------------------------------------------------------------------------
template<int EMITH>
__global__ __launch_bounds__(128) void ln_kernel(
    const float* __restrict__ in, const float* __restrict__ gg,
    const float* __restrict__ bb, float* __restrict__ out,
    __half* __restrict__ outh)
{
    const int row = blockIdx.x, tid = threadIdx.x;
    const float* p = in + (size_t)row * DMODEL;
    float4 v = *(const float4*)(p + tid * 4);
    float s  = v.x + v.y + v.z + v.w;
    float ss = v.x * v.x + v.y * v.y + v.z * v.z + v.w * v.w;
#pragma unroll
    for (int o = 16; o > 0; o >>= 1) {
        s  += __shfl_xor_sync(0xffffffffu, s,  o);
        ss += __shfl_xor_sync(0xffffffffu, ss, o);
    }
    __shared__ float sh[8];
    const int w = tid >> 5, ln = tid & 31;
    if (ln == 0) { sh[w] = s; sh[4 + w] = ss; }
    __syncthreads();
    s  = sh[0] + sh[1] + sh[2] + sh[3];
    ss = sh[4] + sh[5] + sh[6] + sh[7];
    const float mu  = s * (1.0f / DMODEL);
    const float var = ss * (1.0f / DMODEL) - mu * mu;
    const float inv = rsqrtf(var + 1e-5f);
    float4 gv = *(const float4*)(gg + tid * 4);
    float4 bv = *(const float4*)(bb + tid * 4);
    float4 o4;
    o4.x = (v.x - mu) * inv * gv.x + bv.x;
    o4.y = (v.y - mu) * inv * gv.y + bv.y;
    o4.z = (v.z - mu) * inv * gv.z + bv.z;
    o4.w = (v.w - mu) * inv * gv.w + bv.w;
    *(float4*)(out + (size_t)row * DMODEL + tid * 4) = o4;
    if (EMITH) {
        *(__half2*)(outh + (size_t)row * DMODEL + tid * 4)     = __floats2half2_rn(o4.x, o4.y);
        *(__half2*)(outh + (size_t)row * DMODEL + tid * 4 + 2) = __floats2half2_rn(o4.z, o4.w);
    }
}

// ---------------------------------------------------------------------------
extern "C" void kernel_launch(void* const* d_in, const int* in_sizes, int n_in,
                              void* d_out, int out_size)
{
    const float* x      = (const float*)d_in[0];
    const int*   mask   = (const int*)  d_in[1];
    const float* qkv_w  = (const float*)d_in[2];
    const float* qkv_b  = (const float*)d_in[3];
    const float* out_w  = (const float*)d_in[4];
    const float* out_b  = (const float*)d_in[5];
    const float* ffn_w1 = (const float*)d_in[6];
    const float* ffn_b1 = (const float*)d_in[7];
    const float* ffn_w2 = (const float*)d_in[8];
    const float* ffn_b2 = (const float*)d_in[9];
    const float* ln1_g  = (const float*)d_in[10];
    const float* ln1_b  = (const float*)d_in[11];
    const float* ln2_g  = (const float*)d_in[12];
    const float* ln2_b  = (const float*)d_in[13];
    float* out = (float*)d_out;

    __half *qkvh, *attnh, *ffnh, *xh, *x1h, *qkvwT, *outwT, *ffn1T, *ffn2T;
    float *x1p, *prep;
    cudaGetSymbolAddress((void**)&qkvh,  g_qkvh);
    cudaGetSymbolAddress((void**)&attnh, g_attnh);
    cudaGetSymbolAddress((void**)&ffnh,  g_ffnh);
    cudaGetSymbolAddress((void**)&xh,    g_xh);
    cudaGetSymbolAddress((void**)&x1h,   g_x1h);
    cudaGetSymbolAddress((void**)&x1p,   g_x1);
    cudaGetSymbolAddress((void**)&prep,  g_pre);
    cudaGetSymbolAddress((void**)&qkvwT, g_qkvwT);
    cudaGetSymbolAddress((void**)&outwT, g_outwT);
    cudaGetSymbolAddress((void**)&ffn1T, g_ffn1T);
    cudaGetSymbolAddress((void**)&ffn2T, g_ffn2T);

    cudaFuncSetAttribute(hgemm_kernel<0,0,1>, cudaFuncAttributeMaxDynamicSharedMemorySize, GSMEM);
    cudaFuncSetAttribute(hgemm_kernel<0,1,0>, cudaFuncAttributeMaxDynamicSharedMemorySize, GSMEM);
    cudaFuncSetAttribute(hgemm_kernel<1,0,1>, cudaFuncAttributeMaxDynamicSharedMemorySize, GSMEM);

    // 0) One merged prep launch: x->half + 4 weight transposes
    prep_kernel<<<7168, 256>>>(x, qkv_w, out_w, ffn_w1, ffn_w2,
                               xh, qkvwT, outwT, ffn1T, ffn2T);

    // 1) QKV = X @ qkv_w + qkv_b  -> half
    hgemm_kernel<0,0,1><<<dim3(QKV3 / 128, BL / 128), 128, GSMEM>>>(
        xh, qkvwT, qkv_b, nullptr, qkvh, nullptr, BL, QKV3, DMODEL);

    // 2) Attention -> half merged [B,L,D]
    attn_h_kernel<<<512, 128>>>(qkvh, mask, attnh);

    // 3) pre1 = x + (attn @ out_w + out_b) -> f32
    hgemm_kernel<0,1,0><<<dim3(DMODEL / 128, BL / 128), 128, GSMEM>>>(
        attnh, outwT, out_b, x, nullptr, prep, BL, DMODEL, DMODEL);

    // 4) x1 = LN1(pre1) -> f32 + half
    ln_kernel<1><<<BL, 128>>>(prep, ln1_g, ln1_b, x1p, x1h);

    // 5) h = gelu(x1 @ ffn_w1 + ffn_b1) -> half
    hgemm_kernel<1,0,1><<<dim3(FFND / 128, BL / 128), 128, GSMEM>>>(
        x1h, ffn1T, ffn_b1, nullptr, ffnh, nullptr, BL, FFND, DMODEL);

    // 6) pre2 = x1 + (h @ ffn_w2 + ffn_b2) -> f32
    hgemm_kernel<0,1,0><<<dim3(DMODEL / 128, BL / 128), 128, GSMEM>>>(
        ffnh, ffn2T, ffn_b2, x1p, nullptr, prep, BL, DMODEL, FFND);

    // 7) out = LN2(pre2)
    ln_kernel<0><<<BL, 128>>>(prep, ln2_g, ln2_b, out, nullptr);
}

// round 16
// speedup vs baseline: 1.0792x; 1.0792x over previous
#include <cuda_runtime.h>
#include <cuda_fp16.h>
#include <math.h>
#include <stdint.h>
#include <string.h>

#define BQ      4
#define LSEQ    2048
#define DMODEL  512
#define NHEAD   8
#define HDIM    64
#define FFND    2048
#define BL      (BQ * LSEQ)
#define QKV3    (3 * DMODEL)
#define SCHUNK  512

// Scratch (static device globals)
__device__ __half g_qkvh [BL * QKV3];
__device__ __half g_attnh[BL * DMODEL];
__device__ __half g_ffnh [BL * FFND];
__device__ __half g_xh   [BL * DMODEL];
__device__ __half g_x1h  [BL * DMODEL];
__device__ float  g_x1   [BL * DMODEL];
__device__ float  g_pre  [BL * DMODEL];
__device__ __half g_qkvwT[QKV3 * DMODEL];
__device__ __half g_outwT[DMODEL * DMODEL];
__device__ __half g_ffn1T[FFND * DMODEL];
__device__ __half g_ffn2T[DMODEL * FFND];

// ---------------------------------------------------------------------------
__device__ __forceinline__ uint32_t h2u(__half2 h) {
    uint32_t u; memcpy(&u, &h, 4); return u;
}
__device__ __forceinline__ void mma_f16(float* d, const uint32_t* a, const uint32_t* b) {
    asm volatile(
        "mma.sync.aligned.m16n8k16.row.col.f32.f16.f16.f32 "
        "{%0,%1,%2,%3}, {%4,%5,%6,%7}, {%8,%9}, {%0,%1,%2,%3};"
        : "+f"(d[0]), "+f"(d[1]), "+f"(d[2]), "+f"(d[3])
        : "r"(a[0]), "r"(a[1]), "r"(a[2]), "r"(a[3]), "r"(b[0]), "r"(b[1]));
}
__device__ __forceinline__ uint32_t smaddr(const void* p) {
    uint32_t a;
    asm("{.reg .u64 t; cvta.to.shared.u64 t, %1; cvt.u32.u64 %0, t;}" : "=r"(a) : "l"(p));
    return a;
}
#define CP16(dst, src) asm volatile("cp.async.cg.shared.global [%0], [%1], 16;" :: "r"(dst), "l"(src))
#define CPCOMMIT()     asm volatile("cp.async.commit_group;")
#define CPWAIT(n)      asm volatile("cp.async.wait_group %0;" :: "n"(n))
#define LDSM_X4(r0,r1,r2,r3,a) \
    asm volatile("ldmatrix.sync.aligned.m8n8.x4.shared.b16 {%0,%1,%2,%3}, [%4];" \
        : "=r"(r0), "=r"(r1), "=r"(r2), "=r"(r3) : "r"(a))
#define LDSM_X4T(r0,r1,r2,r3,a) \
    asm volatile("ldmatrix.sync.aligned.m8n8.x4.trans.shared.b16 {%0,%1,%2,%3}, [%4];" \
        : "=r"(r0), "=r"(r1), "=r"(r2), "=r"(r3) : "r"(a))

// ---------------------------------------------------------------------------
// FP16 tensor GEMM (R14 config — best measured): 128x128 block, 4 warps
// (2x2), warp tile 64x64, BK=32, 3-stage cp.async, 128 thr, 2 CTAs/SM.
// ---------------------------------------------------------------------------
#define LDA_ 40
#define A_STAGE (128 * LDA_ * 2)
#define NSTAGE  3
#define GSMEM   (2 * NSTAGE * A_STAGE) // 61440

template<int GELU, int HASRES, int OUTH>
__global__ __launch_bounds__(128, 2) void hgemm_kernel(
    const __half* __restrict__ A, const __half* __restrict__ BT,
    const float* __restrict__ bias, const float* __restrict__ res,
    __half* __restrict__ Ch, float* __restrict__ Cf, int M, int N, int K)
{
    extern __shared__ __half smem_dyn[];

    const int tid   = threadIdx.x;
    const int lane  = tid & 31, wid = tid >> 5;
    const int grp   = lane >> 2, qd = lane & 3;
    const int g     = lane >> 3, l7 = lane & 7;
    const int mBase = blockIdx.y * 128;
    const int nBase = blockIdx.x * 128;
    const int mWarp = (wid & 1) * 64;
    const int nWarp = (wid >> 1) * 64;

    const uint32_t aBase = smaddr(smem_dyn);
    const uint32_t bBase = aBase + NSTAGE * A_STAGE;

    const __half* Ap[4]; const __half* Bp[4];
    uint32_t sAo[4], sBo[4];
#pragma unroll
    for (int i = 0; i < 4; i++) {
        const int c = tid + i * 128;
        const int r = c >> 2, s = (c & 3) * 8;
        Ap[i]  = A  + (size_t)(mBase + r) * K + s;
        Bp[i]  = BT + (size_t)(nBase + r) * K + s;
        sAo[i] = aBase + (r * LDA_ + s) * 2;
        sBo[i] = bBase + (r * LDA_ + s) * 2;
    }

    const int rowA = mWarp + (g & 1) * 8 + l7;
    const int kA   = (g >> 1) * 8;
    const int rowB = nWarp + (g >> 1) * 8 + l7;
    const int kB   = (g & 1) * 8;

    float acc[4][8][4];
#pragma unroll
    for (int mt = 0; mt < 4; mt++)
#pragma unroll
        for (int nt = 0; nt < 8; nt++)
#pragma unroll
            for (int f = 0; f < 4; f++) acc[mt][nt][f] = 0.f;

    const int niter = K >> 5;

#pragma unroll
    for (int s = 0; s < NSTAGE - 1; s++) {
        const int k0 = s << 5;
        const uint32_t o = s * A_STAGE;
#pragma unroll
        for (int i = 0; i < 4; i++) {
            CP16(sAo[i] + o, Ap[i] + k0);
            CP16(sBo[i] + o, Bp[i] + k0);
        }
        CPCOMMIT();
    }

    int slot = 0;
    for (int it = 0; it < niter; it++) {
        CPWAIT(NSTAGE - 2);
        __syncthreads();

        if (it + NSTAGE - 1 < niter) {
            const int k0 = (it + NSTAGE - 1) << 5;
            int islot = slot + NSTAGE - 1; if (islot >= NSTAGE) islot -= NSTAGE;
            const uint32_t o = islot * A_STAGE;
#pragma unroll
            for (int i = 0; i < 4; i++) {
                CP16(sAo[i] + o, Ap[i] + k0);
                CP16(sBo[i] + o, Bp[i] + k0);
            }
        }
        CPCOMMIT();

        const uint32_t aS = aBase + slot * A_STAGE;
        const uint32_t bS = bBase + slot * A_STAGE;
#pragma unroll
        for (int ks = 0; ks < 32; ks += 16) {
            uint32_t af[4][4], bf[8][2];
#pragma unroll
            for (int mt = 0; mt < 4; mt++)
                LDSM_X4(af[mt][0], af[mt][1], af[mt][2], af[mt][3],
                        aS + (((rowA + mt * 16) * LDA_) + ks + kA) * 2);
#pragma unroll
            for (int j = 0; j < 4; j++)
                LDSM_X4(bf[2 * j][0], bf[2 * j][1], bf[2 * j + 1][0], bf[2 * j + 1][1],
                        bS + (((rowB + j * 16) * LDA_) + ks + kB) * 2);
#pragma unroll
            for (int mt = 0; mt < 4; mt++)
#pragma unroll
                for (int nt = 0; nt < 8; nt++)
                    mma_f16(acc[mt][nt], af[mt], bf[nt]);
        }
        slot++; if (slot >= NSTAGE) slot = 0;
    }

#pragma unroll
    for (int mt = 0; mt < 4; mt++) {
#pragma unroll
        for (int nt = 0; nt < 8; nt++) {
            const int row = mBase + mWarp + mt * 16 + grp;
            const int col = nBase + nWarp + nt * 8 + qd * 2;
            const float b0 = bias[col], b1 = bias[col + 1];
#pragma unroll
            for (int rr = 0; rr < 2; rr++) {
                const int r = row + rr * 8;
                const size_t base = (size_t)r * N + col;
                float v0 = acc[mt][nt][rr * 2 + 0] + b0;
                float v1 = acc[mt][nt][rr * 2 + 1] + b1;
                if (GELU) {
                    v0 = 0.5f * v0 * (1.0f + erff(v0 * 0.70710678118654752f));
                    v1 = 0.5f * v1 * (1.0f + erff(v1 * 0.70710678118654752f));
                }
                if (HASRES) {
                    float2 rv = *(const float2*)(res + base);
                    v0 += rv.x; v1 += rv.y;
                }
                if (OUTH) {
                    *(__half2*)(Ch + base) = __floats2half2_rn(v0, v1);
                } else {
                    float2 o; o.x = v0; o.y = v1;
                    *(float2*)(Cf + base) = o;
                }
            }
        }
    }
}

// ---------------------------------------------------------------------------
// Merged prep: f2h of x + 4 weight transposes in one launch.
// ---------------------------------------------------------------------------
__global__ __launch_bounds__(256) void prep_kernel(
    const float* __restrict__ x,
    const float* __restrict__ qkv_w, const float* __restrict__ out_w,
    const float* __restrict__ ffn_w1, const float* __restrict__ ffn_w2,
    __half* __restrict__ xh, __half* __restrict__ qkvwT, __half* __restrict__ outwT,
    __half* __restrict__ ffn1T, __half* __restrict__ ffn2T)
{
    int bid = blockIdx.x;
    if (bid < 4096) {
        const int i = bid * 1024 + threadIdx.x * 4;
        float4 v = *(const float4*)(x + i);
        *(__half2*)(xh + i)     = __floats2half2_rn(v.x, v.y);
        *(__half2*)(xh + i + 2) = __floats2half2_rn(v.z, v.w);
        return;
    }
    bid -= 4096;
    const float* in; __half* outp; int C, t, R;
    if (bid < 768)       { in = qkv_w;  outp = qkvwT; R = DMODEL; C = QKV3;   t = bid; }
    else if (bid < 1024) { in = out_w;  outp = outwT; R = DMODEL; C = DMODEL; t = bid - 768; }
    else if (bid < 2048) { in = ffn_w1; outp = ffn1T; R = DMODEL; C = FFND;   t = bid - 1024; }
    else                 { in = ffn_w2; outp = ffn2T; R = FFND;   C = DMODEL; t = bid - 2048; }
    const int tilesC = C >> 5;
    const int cb = (t % tilesC) * 32, rb = (t / tilesC) * 32;

    __shared__ float tt[32][33];
    const int tx = threadIdx.x & 31, ty = threadIdx.x >> 5;
#pragma unroll
    for (int j = 0; j < 4; j++)
        tt[ty + j * 8][tx] = in[(size_t)(rb + ty + j * 8) * C + cb + tx];
    __syncthreads();
#pragma unroll
    for (int j = 0; j < 4; j++)
        outp[(size_t)(cb + ty + j * 8) * R + rb + tx] = __float2half(tt[tx][ty + j * 8]);
}

// ---------------------------------------------------------------------------
// FP16 flash attention (R14 structure): register P, ldmatrix frags, 3-stage
// cp.async KV pipeline, single barrier per tile, wave-balance remap.
// NEW vs R14: base-2 softmax (SCALE2 fold; exp2f replaces __expf).
// ---------------------------------------------------------------------------
#define LDK_ 72
#define KV_STAGE (32 * LDK_ * 2)
#define ANSTG 3
#define SCALE2 0.18033688011112042f   // 0.125 * log2(e)

__device__ __forceinline__ float qmax4(float v) {
    v = fmaxf(v, __shfl_xor_sync(0xffffffffu, v, 1));
    v = fmaxf(v, __shfl_xor_sync(0xffffffffu, v, 2));
    return v;
}
__device__ __forceinline__ float qsum4(float v) {
    v += __shfl_xor_sync(0xffffffffu, v, 1);
    v += __shfl_xor_sync(0xffffffffu, v, 2);
    return v;
}

__global__ __launch_bounds__(128, 2) void attn_h_kernel(
    const __half* __restrict__ qkv, const int* __restrict__ mask,
    __half* __restrict__ out)
{
    __shared__ __half Ks[ANSTG][32 * LDK_];
    __shared__ __half Vs[ANSTG][32 * LDK_];
    __shared__ float biasS[ANSTG][32];

    // Wave-balance remap: idx<256 -> interior chunks c=1,2; else edges c=0,3.
    int idx = blockIdx.x;
    int c, rest;
    if (idx < 256) { c = 1 + (idx & 1); rest = idx >> 1; }
    else           { idx -= 256; c = 3 * (idx & 1); rest = idx >> 1; }
    const int qt = rest & 3;
    const int bh = rest >> 2;
    const int b  = bh >> 3, h = bh & 7;

    const int tid = threadIdx.x, lane = tid & 31, wid = tid >> 5;
    const int grp = lane >> 2, qd = lane & 3;
    const int g   = lane >> 3, l7 = lane & 7;
    const int lq0 = c * SCHUNK + qt * 128 + wid * 32;

    const uint32_t kBase = smaddr(Ks);
    const uint32_t vBase = smaddr(Vs);

    const int rowK = (g >> 1) * 8 + l7;
    const int kK   = (g & 1) * 8;
    const int rowV = (g & 1) * 8 + l7;
    const int colV = (g >> 1) * 8;

    const int stRow = (tid & 63) >> 1;
    const int stSeg = (tid & 1) * 32;
    const int isV   = tid >> 6;
    const uint32_t stDst = (isV ? vBase : kBase) + (stRow * LDK_ + stSeg) * 2;
    const size_t   stSrcOff = (size_t)DMODEL + (size_t)isV * DMODEL + h * HDIM + stSeg;

    uint32_t qa[2][4][4];
#pragma unroll
    for (int mt = 0; mt < 2; mt++)
#pragma unroll
        for (int ks = 0; ks < 4; ks++) {
            const __half* q0 = qkv + (size_t)(b * LSEQ + lq0 + mt * 16 + grp) * QKV3
                               + h * HDIM + ks * 16 + 2 * qd;
            qa[mt][ks][0] = *(const uint32_t*)(q0);
            qa[mt][ks][1] = *(const uint32_t*)(q0 + (size_t)8 * QKV3);
            qa[mt][ks][2] = *(const uint32_t*)(q0 + 8);
            qa[mt][ks][3] = *(const uint32_t*)(q0 + (size_t)8 * QKV3 + 8);
        }

    float O[2][8][4];
#pragma unroll
    for (int mt = 0; mt < 2; mt++)
#pragma unroll
        for (int nt = 0; nt < 8; nt++)
#pragma unroll
            for (int f = 0; f < 4; f++) O[mt][nt][f] = 0.f;
    float mrow[2][2] = {{-1e30f, -1e30f}, {-1e30f, -1e30f}};
    float lrow[2][2] = {{0.f, 0.f}, {0.f, 0.f}};

    int k0 = (c - 1) * SCHUNK; if (k0 < 0) k0 = 0;
    int k1 = (c + 2) * SCHUNK; if (k1 > LSEQ) k1 = LSEQ;
    const int niter = (k1 - k0) >> 5;

#pragma unroll
    for (int s = 0; s < ANSTG - 1; s++) {
        if (s < niter) {
            const int kt = k0 + s * 32;
            const __half* src = qkv + (size_t)(b * LSEQ + kt + stRow) * QKV3 + stSrcOff;
            const uint32_t d = stDst + s * KV_STAGE;
            CP16(d,      src);
            CP16(d + 16, src + 8);
            CP16(d + 32, src + 16);
            CP16(d + 48, src + 24);
            if (tid < 32) biasS[s][tid] = mask[b * LSEQ + kt + tid] ? -1e30f : 0.f;
        }
        CPCOMMIT();
    }

    int slot = 0;
    for (int it = 0; it < niter; it++) {
        CPWAIT(ANSTG - 2);
        __syncthreads();

        if (it + ANSTG - 1 < niter) {
            const int ktn = k0 + (it + ANSTG - 1) * 32;
            int islot = slot + ANSTG - 1; if (islot >= ANSTG) islot -= ANSTG;
            const __half* src = qkv + (size_t)(b * LSEQ + ktn + stRow) * QKV3 + stSrcOff;
            const uint32_t d = stDst + islot * KV_STAGE;
            CP16(d,      src);
            CP16(d + 16, src + 8);
            CP16(d + 32, src + 16);
            CP16(d + 48, src + 24);
            if (tid < 32) biasS[islot][tid] = mask[b * LSEQ + ktn + tid] ? -1e30f : 0.f;
        }
        CPCOMMIT();

        const uint32_t kS = kBase + slot * KV_STAGE;
        const uint32_t vS = vBase + slot * KV_STAGE;

        float sc[2][4][4];
#pragma unroll
        for (int mt = 0; mt < 2; mt++)
#pragma unroll
            for (int nt = 0; nt < 4; nt++)
#pragma unroll
                for (int f = 0; f < 4; f++) sc[mt][nt][f] = 0.f;
#pragma unroll
        for (int ks = 0; ks < 4; ks++) {
            uint32_t kb[4][2];
            LDSM_X4(kb[0][0], kb[0][1], kb[1][0], kb[1][1],
                    kS + ((rowK * LDK_) + ks * 16 + kK) * 2);
            LDSM_X4(kb[2][0], kb[2][1], kb[3][0], kb[3][1],
                    kS + (((rowK + 16) * LDK_) + ks * 16 + kK) * 2);
#pragma unroll
            for (int mt = 0; mt < 2; mt++)
#pragma unroll
                for (int nt = 0; nt < 4; nt++)
                    mma_f16(sc[mt][nt], qa[mt][ks], kb[nt]);
        }

        // scale into log2 domain + mask
        float bs0[4], bs1[4];
#pragma unroll
        for (int nt = 0; nt < 4; nt++) {
            bs0[nt] = biasS[slot][nt * 8 + 2 * qd];
            bs1[nt] = biasS[slot][nt * 8 + 2 * qd + 1];
        }
#pragma unroll
        for (int mt = 0; mt < 2; mt++)
#pragma unroll
            for (int nt = 0; nt < 4; nt++) {
                sc[mt][nt][0] = sc[mt][nt][0] * SCALE2 + bs0[nt];
                sc[mt][nt][1] = sc[mt][nt][1] * SCALE2 + bs1[nt];
                sc[mt][nt][2] = sc[mt][nt][2] * SCALE2 + bs0[nt];
                sc[mt][nt][3] = sc[mt][nt][3] * SCALE2 + bs1[nt];
            }

        float scl[2][2];
#pragma unroll
        for (int mt = 0; mt < 2; mt++) {
            float nm0 = -1e30f, nm1 = -1e30f;
#pragma unroll
            for (int nt = 0; nt < 4; nt++) {
                nm0 = fmaxf(nm0, fmaxf(sc[mt][nt][0], sc[mt][nt][1]));
                nm1 = fmaxf(nm1, fmaxf(sc[mt][nt][2], sc[mt][nt][3]));
            }
            nm0 = qmax4(nm0); nm1 = qmax4(nm1);
            const float m0 = fmaxf(mrow[mt][0], nm0);
            const float m1 = fmaxf(mrow[mt][1], nm1);
            scl[mt][0] = exp2f(mrow[mt][0] - m0);
            scl[mt][1] = exp2f(mrow[mt][1] - m1);
            lrow[mt][0] *= scl[mt][0];
            lrow[mt][1] *= scl[mt][1];
            mrow[mt][0] = m0; mrow[mt][1] = m1;
        }
#pragma unroll
        for (int mt = 0; mt < 2; mt++)
#pragma unroll
            for (int nt = 0; nt < 8; nt++) {
                O[mt][nt][0] *= scl[mt][0];
                O[mt][nt][1] *= scl[mt][0];
                O[mt][nt][2] *= scl[mt][1];
                O[mt][nt][3] *= scl[mt][1];
            }

        uint32_t pf[2][2][4];
        float rs[2][2] = {{0.f, 0.f}, {0.f, 0.f}};
#pragma unroll
        for (int mt = 0; mt < 2; mt++)
#pragma unroll
            for (int nt = 0; nt < 4; nt++) {
                const float p0 = exp2f(sc[mt][nt][0] - mrow[mt][0]);
                const float p1 = exp2f(sc[mt][nt][1] - mrow[mt][0]);
                const float p2 = exp2f(sc[mt][nt][2] - mrow[mt][1]);
                const float p3 = exp2f(sc[mt][nt][3] - mrow[mt][1]);
                rs[mt][0] += p0 + p1;
                rs[mt][1] += p2 + p3;
                const int ks = nt >> 1, hf = nt & 1;
                pf[mt][ks][hf * 2 + 0] = h2u(__floats2half2_rn(p0, p1));
                pf[mt][ks][hf * 2 + 1] = h2u(__floats2half2_rn(p2, p3));
            }
#pragma unroll
        for (int mt = 0; mt < 2; mt++) {
            lrow[mt][0] += qsum4(rs[mt][0]);
            lrow[mt][1] += qsum4(rs[mt][1]);
        }

#pragma unroll
        for (int ks = 0; ks < 2; ks++) {
            uint32_t vb[8][2];
#pragma unroll
            for (int ntp = 0; ntp < 8; ntp += 2)
                LDSM_X4T(vb[ntp][0], vb[ntp][1], vb[ntp + 1][0], vb[ntp + 1][1],
                         vS + (((ks * 16 + rowV) * LDK_) + ntp * 8 + colV) * 2);
#pragma unroll
            for (int mt = 0; mt < 2; mt++)
#pragma unroll
                for (int nt = 0; nt < 8; nt++)
                    mma_f16(O[mt][nt], pf[mt][ks], vb[nt]);
        }
        slot++; if (slot >= ANSTG) slot = 0;
    }

#pragma unroll
    for (int mt = 0; mt < 2; mt++) {
        const float inv0 = 1.0f / lrow[mt][0];
        const float inv1 = 1.0f / lrow[mt][1];
#pragma unroll
        for (int nt = 0; nt < 8; nt++) {
            const int row = lq0 + mt * 16 + grp;
            const int col = h * HDIM + nt * 8 + 2 * qd;
            *(__half2*)(out + (size_t)(b * LSEQ + row) * DMODEL + col) =
                __floats2half2_rn(O[mt][nt][0] * inv0, O[mt][nt][1] * inv0);
            *(__half2*)(out + (size_t)(b * LSEQ + row + 8) * DMODEL + col) =
                __floats2half2_rn(O[mt][nt][2] * inv1, O[mt][nt][3] * inv1);
        }
    }
}

// ---------------------------------------------------------------------------
template<int EMITH>
__global__ __launch_bounds__(128) void ln_kernel(
    const float* __restrict__ in, const float* __restrict__ gg,
    const float* __restrict__ bb, float* __restrict__ out,
    __half* __restrict__ outh)
{
    const int row = blockIdx.x, tid = threadIdx.x;
    const float* p = in + (size_t)row * DMODEL;
    float4 v = *(const float4*)(p + tid * 4);
    float s  = v.x + v.y + v.z + v.w;
    float ss = v.x * v.x + v.y * v.y + v.z * v.z + v.w * v.w;
#pragma unroll
    for (int o = 16; o > 0; o >>= 1) {
        s  += __shfl_xor_sync(0xffffffffu, s,  o);
        ss += __shfl_xor_sync(0xffffffffu, ss, o);
    }
    __shared__ float sh[8];
    const int w = tid >> 5, ln = tid & 31;
    if (ln == 0) { sh[w] = s; sh[4 + w] = ss; }
    __syncthreads();
    s  = sh[0] + sh[1] + sh[2] + sh[3];
    ss = sh[4] + sh[5] + sh[6] + sh[7];
    const float mu  = s * (1.0f / DMODEL);
    const float var = ss * (1.0f / DMODEL) - mu * mu;
    const float inv = rsqrtf(var + 1e-5f);
    float4 gv = *(const float4*)(gg + tid * 4);
    float4 bv = *(const float4*)(bb + tid * 4);
    float4 o4;
    o4.x = (v.x - mu) * inv * gv.x + bv.x;
    o4.y = (v.y - mu) * inv * gv.y + bv.y;
    o4.z = (v.z - mu) * inv * gv.z + bv.z;
    o4.w = (v.w - mu) * inv * gv.w + bv.w;
    *(float4*)(out + (size_t)row * DMODEL + tid * 4) = o4;
    if (EMITH) {
        *(__half2*)(outh + (size_t)row * DMODEL + tid * 4)     = __floats2half2_rn(o4.x, o4.y);
        *(__half2*)(outh + (size_t)row * DMODEL + tid * 4 + 2) = __floats2half2_rn(o4.z, o4.w);
    }
}

// ---------------------------------------------------------------------------
extern "C" void kernel_launch(void* const* d_in, const int* in_sizes, int n_in,
                              void* d_out, int out_size)
{
    const float* x      = (const float*)d_in[0];
    const int*   mask   = (const int*)  d_in[1];
    const float* qkv_w  = (const float*)d_in[2];
    const float* qkv_b  = (const float*)d_in[3];
    const float* out_w  = (const float*)d_in[4];
    const float* out_b  = (const float*)d_in[5];
    const float* ffn_w1 = (const float*)d_in[6];
    const float* ffn_b1 = (const float*)d_in[7];
    const float* ffn_w2 = (const float*)d_in[8];
    const float* ffn_b2 = (const float*)d_in[9];
    const float* ln1_g  = (const float*)d_in[10];
    const float* ln1_b  = (const float*)d_in[11];
    const float* ln2_g  = (const float*)d_in[12];
    const float* ln2_b  = (const float*)d_in[13];
    float* out = (float*)d_out;

    __half *qkvh, *attnh, *ffnh, *xh, *x1h, *qkvwT, *outwT, *ffn1T, *ffn2T;
    float *x1p, *prep;
    cudaGetSymbolAddress((void**)&qkvh,  g_qkvh);
    cudaGetSymbolAddress((void**)&attnh, g_attnh);
    cudaGetSymbolAddress((void**)&ffnh,  g_ffnh);
    cudaGetSymbolAddress((void**)&xh,    g_xh);
    cudaGetSymbolAddress((void**)&x1h,   g_x1h);
    cudaGetSymbolAddress((void**)&x1p,   g_x1);
    cudaGetSymbolAddress((void**)&prep,  g_pre);
    cudaGetSymbolAddress((void**)&qkvwT, g_qkvwT);
    cudaGetSymbolAddress((void**)&outwT, g_outwT);
    cudaGetSymbolAddress((void**)&ffn1T, g_ffn1T);
    cudaGetSymbolAddress((void**)&ffn2T, g_ffn2T);

    cudaFuncSetAttribute(hgemm_kernel<0,0,1>, cudaFuncAttributeMaxDynamicSharedMemorySize, GSMEM);
    cudaFuncSetAttribute(hgemm_kernel<0,1,0>, cudaFuncAttributeMaxDynamicSharedMemorySize, GSMEM);
    cudaFuncSetAttribute(hgemm_kernel<1,0,1>, cudaFuncAttributeMaxDynamicSharedMemorySize, GSMEM);

    // 0) One merged prep launch: x->half + 4 weight transposes
    prep_kernel<<<7168, 256>>>(x, qkv_w, out_w, ffn_w1, ffn_w2,
                               xh, qkvwT, outwT, ffn1T, ffn2T);

    // 1) QKV = X @ qkv_w + qkv_b  -> half
    hgemm_kernel<0,0,1><<<dim3(QKV3 / 128, BL / 128), 128, GSMEM>>>(
        xh, qkvwT, qkv_b, nullptr, qkvh, nullptr, BL, QKV3, DMODEL);

    // 2) Attention -> half merged [B,L,D]
    attn_h_kernel<<<512, 128>>>(qkvh, mask, attnh);

    // 3) pre1 = x + (attn @ out_w + out_b) -> f32
    hgemm_kernel<0,1,0><<<dim3(DMODEL / 128, BL / 128), 128, GSMEM>>>(
        attnh, outwT, out_b, x, nullptr, prep, BL, DMODEL, DMODEL);

    // 4) x1 = LN1(pre1) -> f32 + half
    ln_kernel<1><<<BL, 128>>>(prep, ln1_g, ln1_b, x1p, x1h);

    // 5) h = gelu(x1 @ ffn_w1 + ffn_b1) -> half
    hgemm_kernel<1,0,1><<<dim3(FFND / 128, BL / 128), 128, GSMEM>>>(
        x1h, ffn1T, ffn_b1, nullptr, ffnh, nullptr, BL, FFND, DMODEL);

    // 6) pre2 = x1 + (h @ ffn_w2 + ffn_b2) -> f32
    hgemm_kernel<0,1,0><<<dim3(DMODEL / 128, BL / 128), 128, GSMEM>>>(
        ffnh, ffn2T, ffn_b2, x1p, nullptr, prep, BL, DMODEL, FFND);

    // 7) out = LN2(pre2)
    ln_kernel<0><<<BL, 128>>>(prep, ln2_g, ln2_b, out, nullptr);
}